// round 14
// baseline (speedup 1.0000x reference)
#include <cuda_runtime.h>

// Persistent neural-CDE kernel. 128 CTAs x 512 threads. CTA r owns batch row
// r (gemv/RK4) and W3 column-slice h=r (GEMM). W1/W2/W3-slice in smem.
// R13 champion + : (1) warp-private cp.async ring slots -> GEMM stages need
// only __syncwarp (warps fully decoupled through the GEMM), (2) h2 publish
// fused into gemv2 reduce, (3) 128-thread RK4 update.

#define NCTAS 128
#define NT    512

typedef unsigned long long u64;
typedef unsigned int u32;

__device__ float g_h2T[128 * 128];    // [k][r]
__device__ float g_dz [128 * 128];    // [b][h]
__device__ float g_dx [128 * 3 * 32]; // [b][sel][c]
__device__ u32 g_slot[128];           // per-CTA arrival counters (monotonic)
__device__ u32 g_gen;                 // barrier generation (monotonic)

__device__ __forceinline__ void grid_barrier(u32 target)
{
    __syncthreads();
    if (blockIdx.x == 0) {
        if (threadIdx.x < 32) {
            if (threadIdx.x == 0) {
                __threadfence();   // release our CTA's writes (gpu scope)
                asm volatile("st.release.gpu.b32 [%0], %1;"
                             :: "l"(g_slot), "r"(target) : "memory");
            }
            const u32* p = g_slot + threadIdx.x * 4;
            u32 a, b, c, d; bool ok;
            do {
                asm volatile("ld.relaxed.gpu.v4.b32 {%0,%1,%2,%3}, [%4];"
                             : "=r"(a), "=r"(b), "=r"(c), "=r"(d)
                             : "l"(p) : "memory");
                ok = (a == target) && (b == target) && (c == target) && (d == target);
            } while (!__all_sync(0xffffffffu, ok));
            if (threadIdx.x == 0) {
                asm volatile("fence.acq_rel.gpu;" ::: "memory");
                asm volatile("st.relaxed.gpu.b32 [%0], %1;"
                             :: "l"(&g_gen), "r"(target) : "memory");
            }
        }
    } else {
        if (threadIdx.x == 0) {
            __threadfence();
            asm volatile("st.release.gpu.b32 [%0], %1;"
                         :: "l"(g_slot + blockIdx.x), "r"(target) : "memory");
            u32 g;
            do {
                asm volatile("ld.acquire.gpu.b32 %0, [%1];"
                             : "=r"(g) : "l"(&g_gen) : "memory");
            } while (g != target);
        }
    }
    __syncthreads();
}

// GEMV: out[j] = relu(b[j] + sum_k v[k]*W[k][j]); all operands in smem.
__device__ __forceinline__ void gemv128(const float* __restrict__ vs,
                                        const float* __restrict__ Wsm,
                                        const float* __restrict__ bsm,
                                        float* __restrict__ outv,
                                        float* __restrict__ sp)
{
    const int tid = threadIdx.x;
    const int j = tid & 127, kq = tid >> 7;
    const float* w = Wsm + (kq << 5) * 128 + j;
    const float* v = vs + (kq << 5);
    float acc0 = 0.f, acc1 = 0.f;
    #pragma unroll
    for (int k = 0; k < 32; k += 2) {
        acc0 = fmaf(v[k],     w[ k      * 128], acc0);
        acc1 = fmaf(v[k + 1], w[(k + 1) * 128], acc1);
    }
    sp[(kq << 7) + j] = acc0 + acc1;
    __syncthreads();
    if (tid < 128) {
        float s = bsm[tid] + sp[tid] + sp[128 + tid] + sp[256 + tid] + sp[384 + tid];
        outv[tid] = fmaxf(s, 0.0f);
    }
    __syncthreads();
}

// gemv2: reduce writes relu(.) directly to the global h2T column (fused
// publish). NO trailing syncthreads — grid_barrier A provides ordering.
__device__ __forceinline__ void gemv128_pub(const float* __restrict__ vs,
                                            const float* __restrict__ Wsm,
                                            const float* __restrict__ bsm,
                                            float* __restrict__ gdst, int r,
                                            float* __restrict__ sp)
{
    const int tid = threadIdx.x;
    const int j = tid & 127, kq = tid >> 7;
    const float* w = Wsm + (kq << 5) * 128 + j;
    const float* v = vs + (kq << 5);
    float acc0 = 0.f, acc1 = 0.f;
    #pragma unroll
    for (int k = 0; k < 32; k += 2) {
        acc0 = fmaf(v[k],     w[ k      * 128], acc0);
        acc1 = fmaf(v[k + 1], w[(k + 1) * 128], acc1);
    }
    sp[(kq << 7) + j] = acc0 + acc1;
    __syncthreads();
    if (tid < 128) {
        float s = bsm[tid] + sp[tid] + sp[128 + tid] + sp[256 + tid] + sp[384 + tid];
        gdst[tid * 128 + r] = fmaxf(s, 0.0f);
    }
}

// cephes-style rational tanh: returns p, writes q; tanh(x) = p/q. FMA-only.
__device__ __forceinline__ float tanh_pq(float x, float& qo)
{
    x = fminf(fmaxf(x, -7.90531110591164f), 7.90531110591164f);
    float x2 = x * x;
    float p = fmaf(x2, -2.76076847742355e-16f, 2.00018790482477e-13f);
    p = fmaf(p, x2, -8.60467152213735e-11f);
    p = fmaf(p, x2,  5.12229709037114e-08f);
    p = fmaf(p, x2,  1.48572235717979e-05f);
    p = fmaf(p, x2,  6.37261928875436e-04f);
    p = fmaf(p, x2,  4.89352455891786e-03f);
    p = p * x;
    float q = fmaf(x2, 1.19825839466702e-06f, 1.18534705686654e-04f);
    q = fmaf(q, x2, 2.26843463243900e-03f);
    qo = fmaf(q, x2, 4.89352518554385e-03f);
    return p;
}

// batched reciprocal: 1 MUFU per 4 divisions
__device__ __forceinline__ void rcp4(const float* q, float* inv)
{
    float a01 = q[0] * q[1], a23 = q[2] * q[3], P = a01 * a23, R;
    asm("rcp.approx.f32 %0, %1;" : "=f"(R) : "f"(P));
    inv[0] = R * q[1] * a23;
    inv[1] = R * q[0] * a23;
    inv[2] = R * a01 * q[3];
    inv[3] = R * a01 * q[2];
}

#define CP_ASYNC16(dst, src) \
    asm volatile("cp.async.cg.shared.global [%0], [%1], 16;" \
                 :: "r"(dst), "l"(src) : "memory")
#define CP_COMMIT() asm volatile("cp.async.commit_group;" ::: "memory")
#define CP_WAIT(n)  asm volatile("cp.async.wait_group %0;" :: "n"(n) : "memory")

// smem (floats): w1s 16384 | w2s 16384 | w3s 4096 | hring 16384 | sp 512 |
//                b1s 128 | b2s 128 | ys 128 | zs 128 | kacc 128 | h1s 128 | misc 16
// hring layout: [warp][k][8]  (warp-private slots: rows 8w..8w+7 per k)
#define SMEM_FLOATS (16384*3 + 4096 + 512 + 6*128 + 16)
#define SMEM_BYTES  (SMEM_FLOATS * 4)

extern __shared__ float smem[];

__global__ __launch_bounds__(NT, 1)
void cde_kernel(const float* __restrict__ coeffs,
                const float* __restrict__ W1, const float* __restrict__ b1,
                const float* __restrict__ W2, const float* __restrict__ b2,
                const float* __restrict__ W3, const float* __restrict__ b3,
                const float* __restrict__ Wi, const float* __restrict__ bi,
                const float* __restrict__ Wr, const float* __restrict__ br,
                float* __restrict__ out)
{
    float* w1s   = smem;                // [k][j]
    float* w2s   = w1s  + 16384;
    float* w3s   = w2s  + 16384;        // [k][c] 128x32 (our h's slice)
    float* hring = w3s  + 4096;         // [warp][k][8]
    float* sp    = hring + 16384;
    float* b1s   = sp   + 512;
    float* b2s   = b1s  + 128;
    float* ys    = b2s  + 128;
    float* zs    = ys   + 128;
    float* kacc  = zs   + 128;
    float* h1s   = kacc + 128;
    u32* sbase = (u32*)(h1s + 128);

    const int tid  = threadIdx.x;
    const int wrp  = tid >> 5;
    const int lane = tid & 31;
    const int r    = blockIdx.x;        // owned batch row == owned h-slice

    if (tid == 0) {
        u32 g0;
        asm volatile("ld.relaxed.gpu.b32 %0, [%1];" : "=r"(g0) : "l"(&g_gen));
        *sbase = g0;
    }

    // ---- prologue: stage weights into smem ----
    #pragma unroll
    for (int i = 0; i < 8; i++) {
        int idx = tid + i * NT;
        ((float4*)w1s)[idx] = ((const float4*)W1)[idx];
        ((float4*)w2s)[idx] = ((const float4*)W2)[idx];
    }
    #pragma unroll
    for (int i = 0; i < 2; i++) {
        int idx = tid + i * NT;
        int k = idx >> 3, cq = idx & 7;
        *(float4*)(w3s + k * 32 + cq * 4) =
            *(const float4*)(W3 + k * 4096 + r * 32 + cq * 4);
    }
    if (tid < 128) { b1s[tid] = b1[tid]; b2s[tid] = b2[tid]; }

    // z0 = X(0) @ Wi + bi
    if (tid < 128) {
        const float* ca = coeffs + (size_t)r * 8192;
        float acc = bi[tid];
        #pragma unroll
        for (int c = 0; c < 32; c++)
            acc = fmaf(ca[c], Wi[c * 128 + tid], acc);
        zs[tid] = acc; ys[tid] = acc; kacc[tid] = 0.0f;
    }
    __syncthreads();

    const u32 base = *sbase;
    u32 bno = 0;

    // per-thread GEMM constants: 2 rows x 4 cols
    const int cg = tid & 7, rg = tid >> 3;
    const int r0 = rg << 1;
    const float4 b3q = *(const float4*)(b3 + r * 32 + (cg << 2));
    u64 B01, B23;
    asm("mov.b64 %0, {%1,%2};" : "=l"(B01) : "f"(b3q.x), "f"(b3q.y));
    asm("mov.b64 %0, {%1,%2};" : "=l"(B23) : "f"(b3q.z), "f"(b3q.w));
    const float* ws = w3s + (cg << 2);

    // cp.async mapping: warp wrp copies h rows 8w..8w+7. Lane l covers
    // k = st*16 + (l>>1), half = l&1 (16 bytes each).
    u32 hdst;
    {
        u64 t = __cvta_generic_to_shared(hring);
        hdst = (u32)t + (u32)(wrp * 4096 + (lane >> 1) * 32 + (lane & 1) * 16);
    }
    const char* hsrc = (const char*)g_h2T
                     + (size_t)(lane >> 1) * 512 + wrp * 32 + (lane & 1) * 16;
    // GEMM h reads: warp-private slot, row pair (rg&3)
    const float* hwarp = hring + wrp * 1024 + (rg & 3) * 2;

    for (int s = 0; s < 64; s++) {
        // publish dX for this segment (f=0, f=0.5, f=1)
        if (tid < 32) {
            const float* bc = coeffs + (size_t)r * 8192 + s * 128;
            int c = tid;
            float cb = bc[32 + c], c2 = bc[64 + c], c3 = bc[96 + c];
            g_dx[(r * 3 + 0) * 32 + c] = cb;
            g_dx[(r * 3 + 1) * 32 + c] = fmaf(0.25f, c3, fmaf(0.5f, c2, cb));
            g_dx[(r * 3 + 2) * 32 + c] = (s < 63) ? bc[128 + 32 + c]
                                                  : (cb + c2 + c3);
        }

        for (int stage = 0; stage < 4; stage++) {
            // ---- row-owner: layers 1,2 on own row; publish fused ----
            gemv128(ys, w1s, b1s, h1s, sp);
            gemv128_pub(h1s, w2s, b2s, g_h2T, r, sp);

            grid_barrier(base + (++bno));   // A: all h2 rows + dX published

            // ---- kick off ALL 8 cp.async stages (warp-private slots) ----
            #pragma unroll
            for (int st = 0; st < 8; st++) {
                CP_ASYNC16(hdst + st * 512, hsrc + st * 8192);
                CP_COMMIT();
            }

            // dX loads: L2 latency hides under the first GEMM stages
            const int sel = (stage == 0) ? 0 : ((stage == 3) ? 2 : 1);
            float4 dA = *(const float4*)(g_dx + (r0 * 3 + sel) * 32 + (cg << 2));
            float4 dB = *(const float4*)(g_dx + ((r0 + 1) * 3 + sel) * 32 + (cg << 2));

            // ---- GEMM: warp-decoupled ring consumption, FFMA2 ----
            u64 A01 = B01, A23 = B23;   // row r0,   cols (0,1) (2,3)
            u64 E01 = B01, E23 = B23;   // row r0+1
            #define GSTAGE(BB)                                                       \
            {   CP_WAIT(7 - (BB));                                                   \
                __syncwarp();                                                        \
                const float* hb = hwarp + (BB) * 128;                                \
                const float* wb = ws + (BB) * 512;                                   \
                _Pragma("unroll")                                                    \
                for (int kk = 0; kk < 16; kk++) {                                    \
                    float2 h = *(const float2*)(hb + kk * 8);                        \
                    float4 w = *(const float4*)(wb + kk * 32);                       \
                    u64 w01, w23, hx2, hy2;                                          \
                    asm("mov.b64 %0, {%1,%2};" : "=l"(w01) : "f"(w.x), "f"(w.y));    \
                    asm("mov.b64 %0, {%1,%2};" : "=l"(w23) : "f"(w.z), "f"(w.w));    \
                    asm("mov.b64 %0, {%1,%1};" : "=l"(hx2) : "f"(h.x));              \
                    asm("mov.b64 %0, {%1,%1};" : "=l"(hy2) : "f"(h.y));              \
                    asm("fma.rn.f32x2 %0,%1,%2,%0;" : "+l"(A01) : "l"(w01), "l"(hx2)); \
                    asm("fma.rn.f32x2 %0,%1,%2,%0;" : "+l"(A23) : "l"(w23), "l"(hx2)); \
                    asm("fma.rn.f32x2 %0,%1,%2,%0;" : "+l"(E01) : "l"(w01), "l"(hy2)); \
                    asm("fma.rn.f32x2 %0,%1,%2,%0;" : "+l"(E23) : "l"(w23), "l"(hy2)); \
                }                                                                    \
            }
            GSTAGE(0) GSTAGE(1) GSTAGE(2) GSTAGE(3)
            GSTAGE(4) GSTAGE(5) GSTAGE(6) GSTAGE(7)
            #undef GSTAGE

            float a0, a1, a2, a3, e0, e1, e2, e3;
            asm("mov.b64 {%0,%1}, %2;" : "=f"(a0), "=f"(a1) : "l"(A01));
            asm("mov.b64 {%0,%1}, %2;" : "=f"(a2), "=f"(a3) : "l"(A23));
            asm("mov.b64 {%0,%1}, %2;" : "=f"(e0), "=f"(e1) : "l"(E01));
            asm("mov.b64 {%0,%1}, %2;" : "=f"(e2), "=f"(e3) : "l"(E23));

            // ---- tanh (rational, batched rcp) + contraction with dX ----
            float p[8], q[8], inv[8];
            p[0] = tanh_pq(a0, q[0]); p[1] = tanh_pq(a1, q[1]);
            p[2] = tanh_pq(a2, q[2]); p[3] = tanh_pq(a3, q[3]);
            p[4] = tanh_pq(e0, q[4]); p[5] = tanh_pq(e1, q[5]);
            p[6] = tanh_pq(e2, q[6]); p[7] = tanh_pq(e3, q[7]);
            rcp4(q,     inv);
            rcp4(q + 4, inv + 4);

            float pr0 = p[0]*inv[0]*dA.x + p[1]*inv[1]*dA.y
                      + p[2]*inv[2]*dA.z + p[3]*inv[3]*dA.w;
            float pr1 = p[4]*inv[4]*dB.x + p[5]*inv[5]*dB.y
                      + p[6]*inv[6]*dB.z + p[7]*inv[7]*dB.w;
            #pragma unroll
            for (int off = 4; off >= 1; off >>= 1) {
                pr0 += __shfl_down_sync(0xffffffffu, pr0, off);
                pr1 += __shfl_down_sync(0xffffffffu, pr1, off);
            }
            if (cg == 0) {
                g_dz[ r0      * 128 + r] = pr0;
                g_dz[(r0 + 1) * 128 + r] = pr1;
            }

            grid_barrier(base + (++bno));   // B: dz complete

            // ---- row-owner: RK4 stage update (128 threads) ----
            if (tid < 128) {
                float dz = g_dz[r * 128 + tid];
                float kv = kacc[tid];
                float zq = zs[tid];
                float kw = (stage == 0 || stage == 3) ? 1.0f : 2.0f;
                kv = fmaf(kw, dz, kv);
                if (stage < 3) {
                    ys[tid] = fmaf((stage == 2) ? 1.0f : 0.5f, dz, zq);
                    kacc[tid] = kv;
                } else {
                    float zn = fmaf(1.0f / 6.0f, kv, zq);
                    zs[tid] = zn; ys[tid] = zn; kacc[tid] = 0.0f;
                }
            }
            __syncthreads();
        }
    }

    // ---- readout: out[r] = sigmoid(z @ Wr + br) ----
    if (tid < 32) {
        float part = 0.0f;
        #pragma unroll
        for (int h = tid; h < 128; h += 32)
            part = fmaf(zs[h], Wr[h], part);
        #pragma unroll
        for (int off = 16; off >= 1; off >>= 1)
            part += __shfl_down_sync(0xffffffffu, part, off);
        if (tid == 0)
            out[r] = 1.0f / (1.0f + __expf(-(part + br[0])));
    }
}

extern "C" void kernel_launch(void* const* d_in, const int* in_sizes, int n_in,
                              void* d_out, int out_size)
{
    const float* coeffs = (const float*)d_in[0];
    const float* W1 = (const float*)d_in[1];
    const float* b1 = (const float*)d_in[2];
    const float* W2 = (const float*)d_in[3];
    const float* b2 = (const float*)d_in[4];
    const float* W3 = (const float*)d_in[5];
    const float* b3 = (const float*)d_in[6];
    const float* Wi = (const float*)d_in[7];
    const float* bi = (const float*)d_in[8];
    const float* Wr = (const float*)d_in[9];
    const float* br = (const float*)d_in[10];
    float* out = (float*)d_out;

    cudaFuncSetAttribute(cde_kernel,
                         cudaFuncAttributeMaxDynamicSharedMemorySize, SMEM_BYTES);
    cde_kernel<<<NCTAS, NT, SMEM_BYTES>>>(coeffs, W1, b1, W2, b2, W3, b3,
                                          Wi, bi, Wr, br, out);
}

// round 15
// speedup vs baseline: 1.0996x; 1.0996x over previous
#include <cuda_runtime.h>

// Persistent neural-CDE kernel. 128 CTAs x 512 threads. CTA r owns batch row
// r (gemv/RK4) and W3 column-slice h=r (GEMM). W1/W2/W3-slice in smem.
// R13 champion + (1) fused h2 publish, (2) 128-thread RK4, (3) cp.async ring
// re-chunked to 4 stages x 32 k (half the wait/sync points, identical
// coalesced copy pattern and k-order).

#define NCTAS 128
#define NT    512

typedef unsigned long long u64;
typedef unsigned int u32;

__device__ float g_h2T[128 * 128];    // [k][r]
__device__ float g_dz [128 * 128];    // [b][h]
__device__ float g_dx [128 * 3 * 32]; // [b][sel][c]
__device__ u32 g_slot[128];           // per-CTA arrival counters (monotonic)
__device__ u32 g_gen;                 // barrier generation (monotonic)

__device__ __forceinline__ void grid_barrier(u32 target)
{
    __syncthreads();
    if (blockIdx.x == 0) {
        if (threadIdx.x < 32) {
            if (threadIdx.x == 0) {
                __threadfence();   // release our CTA's writes (gpu scope)
                asm volatile("st.release.gpu.b32 [%0], %1;"
                             :: "l"(g_slot), "r"(target) : "memory");
            }
            const u32* p = g_slot + threadIdx.x * 4;
            u32 a, b, c, d; bool ok;
            do {
                asm volatile("ld.relaxed.gpu.v4.b32 {%0,%1,%2,%3}, [%4];"
                             : "=r"(a), "=r"(b), "=r"(c), "=r"(d)
                             : "l"(p) : "memory");
                ok = (a == target) && (b == target) && (c == target) && (d == target);
            } while (!__all_sync(0xffffffffu, ok));
            if (threadIdx.x == 0) {
                asm volatile("fence.acq_rel.gpu;" ::: "memory");
                asm volatile("st.relaxed.gpu.b32 [%0], %1;"
                             :: "l"(&g_gen), "r"(target) : "memory");
            }
        }
    } else {
        if (threadIdx.x == 0) {
            __threadfence();
            asm volatile("st.release.gpu.b32 [%0], %1;"
                         :: "l"(g_slot + blockIdx.x), "r"(target) : "memory");
            u32 g;
            do {
                asm volatile("ld.acquire.gpu.b32 %0, [%1];"
                             : "=r"(g) : "l"(&g_gen) : "memory");
            } while (g != target);
        }
    }
    __syncthreads();
}

// GEMV: out[j] = relu(b[j] + sum_k v[k]*W[k][j]); all operands in smem.
__device__ __forceinline__ void gemv128(const float* __restrict__ vs,
                                        const float* __restrict__ Wsm,
                                        const float* __restrict__ bsm,
                                        float* __restrict__ outv,
                                        float* __restrict__ sp)
{
    const int tid = threadIdx.x;
    const int j = tid & 127, kq = tid >> 7;
    const float* w = Wsm + (kq << 5) * 128 + j;
    const float* v = vs + (kq << 5);
    float acc0 = 0.f, acc1 = 0.f;
    #pragma unroll
    for (int k = 0; k < 32; k += 2) {
        acc0 = fmaf(v[k],     w[ k      * 128], acc0);
        acc1 = fmaf(v[k + 1], w[(k + 1) * 128], acc1);
    }
    sp[(kq << 7) + j] = acc0 + acc1;
    __syncthreads();
    if (tid < 128) {
        float s = bsm[tid] + sp[tid] + sp[128 + tid] + sp[256 + tid] + sp[384 + tid];
        outv[tid] = fmaxf(s, 0.0f);
    }
    __syncthreads();
}

// gemv2: reduce writes relu(.) directly to the global h2T column (fused
// publish). NO trailing syncthreads — grid_barrier A provides ordering.
__device__ __forceinline__ void gemv128_pub(const float* __restrict__ vs,
                                            const float* __restrict__ Wsm,
                                            const float* __restrict__ bsm,
                                            float* __restrict__ gdst, int r,
                                            float* __restrict__ sp)
{
    const int tid = threadIdx.x;
    const int j = tid & 127, kq = tid >> 7;
    const float* w = Wsm + (kq << 5) * 128 + j;
    const float* v = vs + (kq << 5);
    float acc0 = 0.f, acc1 = 0.f;
    #pragma unroll
    for (int k = 0; k < 32; k += 2) {
        acc0 = fmaf(v[k],     w[ k      * 128], acc0);
        acc1 = fmaf(v[k + 1], w[(k + 1) * 128], acc1);
    }
    sp[(kq << 7) + j] = acc0 + acc1;
    __syncthreads();
    if (tid < 128) {
        float s = bsm[tid] + sp[tid] + sp[128 + tid] + sp[256 + tid] + sp[384 + tid];
        gdst[tid * 128 + r] = fmaxf(s, 0.0f);
    }
}

// cephes-style rational tanh: returns p, writes q; tanh(x) = p/q. FMA-only.
__device__ __forceinline__ float tanh_pq(float x, float& qo)
{
    x = fminf(fmaxf(x, -7.90531110591164f), 7.90531110591164f);
    float x2 = x * x;
    float p = fmaf(x2, -2.76076847742355e-16f, 2.00018790482477e-13f);
    p = fmaf(p, x2, -8.60467152213735e-11f);
    p = fmaf(p, x2,  5.12229709037114e-08f);
    p = fmaf(p, x2,  1.48572235717979e-05f);
    p = fmaf(p, x2,  6.37261928875436e-04f);
    p = fmaf(p, x2,  4.89352455891786e-03f);
    p = p * x;
    float q = fmaf(x2, 1.19825839466702e-06f, 1.18534705686654e-04f);
    q = fmaf(q, x2, 2.26843463243900e-03f);
    qo = fmaf(q, x2, 4.89352518554385e-03f);
    return p;
}

// batched reciprocal: 1 MUFU per 4 divisions
__device__ __forceinline__ void rcp4(const float* q, float* inv)
{
    float a01 = q[0] * q[1], a23 = q[2] * q[3], P = a01 * a23, R;
    asm("rcp.approx.f32 %0, %1;" : "=f"(R) : "f"(P));
    inv[0] = R * q[1] * a23;
    inv[1] = R * q[0] * a23;
    inv[2] = R * a01 * q[3];
    inv[3] = R * a01 * q[2];
}

#define CP_ASYNC16(dst, src) \
    asm volatile("cp.async.cg.shared.global [%0], [%1], 16;" \
                 :: "r"(dst), "l"(src) : "memory")
#define CP_COMMIT() asm volatile("cp.async.commit_group;" ::: "memory")
#define CP_WAIT(n)  asm volatile("cp.async.wait_group %0;" :: "n"(n) : "memory")

// smem (floats): w1s 16384 | w2s 16384 | w3s 4096 | hring 16384 | sp 512 |
//                b1s 128 | b2s 128 | ys 128 | zs 128 | kacc 128 | h1s 128 | misc 16
// hring: [k][b] 128x128, consumed as 4 stages of 32 k.
#define SMEM_FLOATS (16384*3 + 4096 + 512 + 6*128 + 16)
#define SMEM_BYTES  (SMEM_FLOATS * 4)

extern __shared__ float smem[];

__global__ __launch_bounds__(NT, 1)
void cde_kernel(const float* __restrict__ coeffs,
                const float* __restrict__ W1, const float* __restrict__ b1,
                const float* __restrict__ W2, const float* __restrict__ b2,
                const float* __restrict__ W3, const float* __restrict__ b3,
                const float* __restrict__ Wi, const float* __restrict__ bi,
                const float* __restrict__ Wr, const float* __restrict__ br,
                float* __restrict__ out)
{
    float* w1s   = smem;                // [k][j]
    float* w2s   = w1s  + 16384;
    float* w3s   = w2s  + 16384;        // [k][c] 128x32 (our h's slice)
    float* hring = w3s  + 4096;         // [k][b] 128x128
    float* sp    = hring + 16384;
    float* b1s   = sp   + 512;
    float* b2s   = b1s  + 128;
    float* ys    = b2s  + 128;
    float* zs    = ys   + 128;
    float* kacc  = zs   + 128;
    float* h1s   = kacc + 128;
    u32* sbase = (u32*)(h1s + 128);

    const int tid = threadIdx.x;
    const int r   = blockIdx.x;         // owned batch row == owned h-slice

    if (tid == 0) {
        u32 g0;
        asm volatile("ld.relaxed.gpu.b32 %0, [%1];" : "=r"(g0) : "l"(&g_gen));
        *sbase = g0;
    }

    // ---- prologue: stage weights into smem ----
    #pragma unroll
    for (int i = 0; i < 8; i++) {
        int idx = tid + i * NT;
        ((float4*)w1s)[idx] = ((const float4*)W1)[idx];
        ((float4*)w2s)[idx] = ((const float4*)W2)[idx];
    }
    #pragma unroll
    for (int i = 0; i < 2; i++) {
        int idx = tid + i * NT;
        int k = idx >> 3, cq = idx & 7;
        *(float4*)(w3s + k * 32 + cq * 4) =
            *(const float4*)(W3 + k * 4096 + r * 32 + cq * 4);
    }
    if (tid < 128) { b1s[tid] = b1[tid]; b2s[tid] = b2[tid]; }

    // z0 = X(0) @ Wi + bi
    if (tid < 128) {
        const float* ca = coeffs + (size_t)r * 8192;
        float acc = bi[tid];
        #pragma unroll
        for (int c = 0; c < 32; c++)
            acc = fmaf(ca[c], Wi[c * 128 + tid], acc);
        zs[tid] = acc; ys[tid] = acc; kacc[tid] = 0.0f;
    }
    __syncthreads();

    const u32 base = *sbase;
    u32 bno = 0;

    // per-thread GEMM constants: 2 rows x 4 cols
    const int cg = tid & 7, rg = tid >> 3;
    const int r0 = rg << 1;
    const float4 b3q = *(const float4*)(b3 + r * 32 + (cg << 2));
    u64 B01, B23;
    asm("mov.b64 %0, {%1,%2};" : "=l"(B01) : "f"(b3q.x), "f"(b3q.y));
    asm("mov.b64 %0, {%1,%2};" : "=l"(B23) : "f"(b3q.z), "f"(b3q.w));
    const float* ws = w3s + (cg << 2);
    u32 hdst;
    {
        u64 t = __cvta_generic_to_shared(hring);
        hdst = (u32)t + (u32)tid * 16;     // coalesced: warp = one 512B k-row
    }
    const char* hsrc = (const char*)g_h2T + (size_t)tid * 16;

    for (int s = 0; s < 64; s++) {
        // publish dX for this segment (f=0, f=0.5, f=1)
        if (tid < 32) {
            const float* bc = coeffs + (size_t)r * 8192 + s * 128;
            int c = tid;
            float cb = bc[32 + c], c2 = bc[64 + c], c3 = bc[96 + c];
            g_dx[(r * 3 + 0) * 32 + c] = cb;
            g_dx[(r * 3 + 1) * 32 + c] = fmaf(0.25f, c3, fmaf(0.5f, c2, cb));
            g_dx[(r * 3 + 2) * 32 + c] = (s < 63) ? bc[128 + 32 + c]
                                                  : (cb + c2 + c3);
        }

        for (int stage = 0; stage < 4; stage++) {
            // ---- row-owner: layers 1,2 on own row; publish fused ----
            gemv128(ys, w1s, b1s, h1s, sp);
            gemv128_pub(h1s, w2s, b2s, g_h2T, r, sp);

            grid_barrier(base + (++bno));   // A: all h2 rows + dX published

            // ---- kick off all 4 cp.async stages (32 k = 16 KB each;
            //      each thread: 2 contiguous 16B chunks, 1 commit group) ----
            #pragma unroll
            for (int st = 0; st < 4; st++) {
                CP_ASYNC16(hdst + st * 16384,        hsrc + st * 16384);
                CP_ASYNC16(hdst + st * 16384 + 8192, hsrc + st * 16384 + 8192);
                CP_COMMIT();
            }

            // dX loads: L2 latency hides under the first GEMM stage wait
            const int sel = (stage == 0) ? 0 : ((stage == 3) ? 2 : 1);
            float4 dA = *(const float4*)(g_dx + (r0 * 3 + sel) * 32 + (cg << 2));
            float4 dB = *(const float4*)(g_dx + ((r0 + 1) * 3 + sel) * 32 + (cg << 2));

            // ---- GEMM: consume ring stages, FFMA2 ----
            u64 A01 = B01, A23 = B23;   // row r0,   cols (0,1) (2,3)
            u64 E01 = B01, E23 = B23;   // row r0+1
            #define GSTAGE(BB)                                                       \
            {   CP_WAIT(3 - (BB));                                                   \
                __syncthreads();                                                     \
                const float* hb = hring + (BB) * 4096 + r0;                          \
                const float* wb = ws + (BB) * 1024;                                  \
                _Pragma("unroll")                                                    \
                for (int kk = 0; kk < 32; kk++) {                                    \
                    float2 h = *(const float2*)(hb + kk * 128);                      \
                    float4 w = *(const float4*)(wb + kk * 32);                       \
                    u64 w01, w23, hx2, hy2;                                          \
                    asm("mov.b64 %0, {%1,%2};" : "=l"(w01) : "f"(w.x), "f"(w.y));    \
                    asm("mov.b64 %0, {%1,%2};" : "=l"(w23) : "f"(w.z), "f"(w.w));    \
                    asm("mov.b64 %0, {%1,%1};" : "=l"(hx2) : "f"(h.x));              \
                    asm("mov.b64 %0, {%1,%1};" : "=l"(hy2) : "f"(h.y));              \
                    asm("fma.rn.f32x2 %0,%1,%2,%0;" : "+l"(A01) : "l"(w01), "l"(hx2)); \
                    asm("fma.rn.f32x2 %0,%1,%2,%0;" : "+l"(A23) : "l"(w23), "l"(hx2)); \
                    asm("fma.rn.f32x2 %0,%1,%2,%0;" : "+l"(E01) : "l"(w01), "l"(hy2)); \
                    asm("fma.rn.f32x2 %0,%1,%2,%0;" : "+l"(E23) : "l"(w23), "l"(hy2)); \
                }                                                                    \
            }
            GSTAGE(0) GSTAGE(1) GSTAGE(2) GSTAGE(3)
            #undef GSTAGE

            float a0, a1, a2, a3, e0, e1, e2, e3;
            asm("mov.b64 {%0,%1}, %2;" : "=f"(a0), "=f"(a1) : "l"(A01));
            asm("mov.b64 {%0,%1}, %2;" : "=f"(a2), "=f"(a3) : "l"(A23));
            asm("mov.b64 {%0,%1}, %2;" : "=f"(e0), "=f"(e1) : "l"(E01));
            asm("mov.b64 {%0,%1}, %2;" : "=f"(e2), "=f"(e3) : "l"(E23));

            // ---- tanh (rational, batched rcp) + contraction with dX ----
            float p[8], q[8], inv[8];
            p[0] = tanh_pq(a0, q[0]); p[1] = tanh_pq(a1, q[1]);
            p[2] = tanh_pq(a2, q[2]); p[3] = tanh_pq(a3, q[3]);
            p[4] = tanh_pq(e0, q[4]); p[5] = tanh_pq(e1, q[5]);
            p[6] = tanh_pq(e2, q[6]); p[7] = tanh_pq(e3, q[7]);
            rcp4(q,     inv);
            rcp4(q + 4, inv + 4);

            float pr0 = p[0]*inv[0]*dA.x + p[1]*inv[1]*dA.y
                      + p[2]*inv[2]*dA.z + p[3]*inv[3]*dA.w;
            float pr1 = p[4]*inv[4]*dB.x + p[5]*inv[5]*dB.y
                      + p[6]*inv[6]*dB.z + p[7]*inv[7]*dB.w;
            #pragma unroll
            for (int off = 4; off >= 1; off >>= 1) {
                pr0 += __shfl_down_sync(0xffffffffu, pr0, off);
                pr1 += __shfl_down_sync(0xffffffffu, pr1, off);
            }
            if (cg == 0) {
                g_dz[ r0      * 128 + r] = pr0;
                g_dz[(r0 + 1) * 128 + r] = pr1;
            }

            grid_barrier(base + (++bno));   // B: dz complete

            // ---- row-owner: RK4 stage update (128 threads, coalesced) ----
            if (tid < 128) {
                float dz = g_dz[r * 128 + tid];
                float kv = kacc[tid];
                float zq = zs[tid];
                float kw = (stage == 0 || stage == 3) ? 1.0f : 2.0f;
                kv = fmaf(kw, dz, kv);
                if (stage < 3) {
                    ys[tid] = fmaf((stage == 2) ? 1.0f : 0.5f, dz, zq);
                    kacc[tid] = kv;
                } else {
                    float zn = fmaf(1.0f / 6.0f, kv, zq);
                    zs[tid] = zn; ys[tid] = zn; kacc[tid] = 0.0f;
                }
            }
            __syncthreads();
        }
    }

    // ---- readout: out[r] = sigmoid(z @ Wr + br) ----
    if (tid < 32) {
        float part = 0.0f;
        #pragma unroll
        for (int h = tid; h < 128; h += 32)
            part = fmaf(zs[h], Wr[h], part);
        #pragma unroll
        for (int off = 16; off >= 1; off >>= 1)
            part += __shfl_down_sync(0xffffffffu, part, off);
        if (tid == 0)
            out[r] = 1.0f / (1.0f + __expf(-(part + br[0])));
    }
}

extern "C" void kernel_launch(void* const* d_in, const int* in_sizes, int n_in,
                              void* d_out, int out_size)
{
    const float* coeffs = (const float*)d_in[0];
    const float* W1 = (const float*)d_in[1];
    const float* b1 = (const float*)d_in[2];
    const float* W2 = (const float*)d_in[3];
    const float* b2 = (const float*)d_in[4];
    const float* W3 = (const float*)d_in[5];
    const float* b3 = (const float*)d_in[6];
    const float* Wi = (const float*)d_in[7];
    const float* bi = (const float*)d_in[8];
    const float* Wr = (const float*)d_in[9];
    const float* br = (const float*)d_in[10];
    float* out = (float*)d_out;

    cudaFuncSetAttribute(cde_kernel,
                         cudaFuncAttributeMaxDynamicSharedMemorySize, SMEM_BYTES);
    cde_kernel<<<NCTAS, NT, SMEM_BYTES>>>(coeffs, W1, b1, W2, b2, W3, b3,
                                          Wi, bi, Wr, br, out);
}